// round 1
// baseline (speedup 1.0000x reference)
#include <cuda_runtime.h>
#include <cstdint>

#define B_    4
#define N_    1000
#define T_    12
#define D_    64
#define HID_  128
#define EF_   64
#define E_    64000
#define SEG_  (B_*N_)       // 4000
#define ROWS_ (SEG_*T_)     // 48000
#define TD_   (T_*D_)       // 768
#define TH_   (T_*HID_)     // 1536

typedef unsigned long long u64;

// ---------------- device scratch (no allocations allowed) ----------------
__device__ float g_S1[ROWS_ * HID_];   // x@A1 + (A1_b+A2_b), [node*T][HID]
__device__ float g_S2[ROWS_ * HID_];   // x@A2
__device__ int   g_cnt[2 * SEG_];
__device__ int   g_off[2 * (SEG_ + 1)];
__device__ int   g_cur[2 * SEG_];
__device__ int   g_csr_s[E_];
__device__ int   g_csr_r[E_];

// ---------------- f32x2 packed helpers (sm_100+ only) ----------------
__device__ __forceinline__ void fma2(u64 &d, u64 a, u64 b) {
    asm("fma.rn.f32x2 %0, %1, %2, %0;" : "+l"(d) : "l"(a), "l"(b));
}
__device__ __forceinline__ u64 pack2(float x, float y) {
    u64 r; asm("mov.b64 %0, {%1, %2};" : "=l"(r) : "f"(x), "f"(y)); return r;
}
__device__ __forceinline__ float2 unpack2(u64 v) {
    float2 r; asm("mov.b64 {%0, %1}, %2;" : "=f"(r.x), "=f"(r.y) : "l"(v)); return r;
}

// ---------------- CSR build ----------------
__global__ void k_zero() {
    int i = blockIdx.x * blockDim.x + threadIdx.x;
    if (i < 2 * SEG_) g_cnt[i] = 0;
}

__global__ void k_count(const int* __restrict__ bi, const int* __restrict__ si,
                        const int* __restrict__ ri) {
    int e = blockIdx.x * blockDim.x + threadIdx.x;
    if (e >= E_) return;
    int b = bi[e];
    atomicAdd(&g_cnt[b * N_ + si[e]], 1);
    atomicAdd(&g_cnt[SEG_ + b * N_ + ri[e]], 1);
}

// single-block exclusive scan of 4000 counts (which: 0=send, 1=recv)
__global__ void k_scan(int which) {
    const int* cnt = g_cnt + which * SEG_;
    int* off = g_off + which * (SEG_ + 1);
    int* cur = g_cur + which * SEG_;
    __shared__ int part[1024];
    int tid = threadIdx.x;
    int l[4]; int s = 0;
#pragma unroll
    for (int j = 0; j < 4; j++) {
        int idx = tid * 4 + j;
        l[j] = (idx < SEG_) ? cnt[idx] : 0;
        s += l[j];
    }
    part[tid] = s;
    __syncthreads();
    for (int o = 1; o < 1024; o <<= 1) {
        int v = part[tid];
        int a = (tid >= o) ? part[tid - o] : 0;
        __syncthreads();
        part[tid] = v + a;
        __syncthreads();
    }
    int run = (tid > 0) ? part[tid - 1] : 0;
#pragma unroll
    for (int j = 0; j < 4; j++) {
        int idx = tid * 4 + j;
        if (idx < SEG_) { off[idx] = run; cur[idx] = run; run += l[j]; }
    }
    if (tid == 1023) off[SEG_] = part[1023];
}

__global__ void k_scatter(const int* __restrict__ bi, const int* __restrict__ si,
                          const int* __restrict__ ri) {
    int e = blockIdx.x * blockDim.x + threadIdx.x;
    if (e >= E_) return;
    int b = bi[e];
    int ps = atomicAdd(&g_cur[b * N_ + si[e]], 1);
    g_csr_s[ps] = e;
    int pr = atomicAdd(&g_cur[SEG_ + b * N_ + ri[e]], 1);
    g_csr_r[pr] = e;
}

// ---------------- node projection: S1 = x@A1 + (A1_b+A2_b), S2 = x@A2 ----------------
// grid 750 blocks x 128 threads; each block does 64 rows in 16 passes of 4.
__global__ void k_nodeproj(const float* __restrict__ x,
                           const float* __restrict__ A1w, const float* __restrict__ A1b,
                           const float* __restrict__ A2w, const float* __restrict__ A2b) {
    __shared__ float xsh[4 * 64];
    int tid = threadIdx.x;                 // 0..127  = output column h
    float b12 = A1b[tid] + A2b[tid];
    int rowBase = blockIdx.x * 64;
    for (int p = 0; p < 16; p++) {
        int r0 = rowBase + p * 4;
        __syncthreads();
        for (int i = tid; i < 256; i += 128) xsh[i] = x[(size_t)r0 * 64 + i];
        __syncthreads();
        float a1[4] = {b12, b12, b12, b12};
        float a2[4] = {0.f, 0.f, 0.f, 0.f};
#pragma unroll 8
        for (int d = 0; d < 64; d++) {
            float w1 = A1w[d * 128 + tid];
            float w2 = A2w[d * 128 + tid];
#pragma unroll
            for (int r = 0; r < 4; r++) {
                float xv = xsh[r * 64 + d];
                a1[r] = fmaf(xv, w1, a1[r]);
                a2[r] = fmaf(xv, w2, a2[r]);
            }
        }
#pragma unroll
        for (int r = 0; r < 4; r++) {
            g_S1[(size_t)(r0 + r) * 128 + tid] = a1[r];
            g_S2[(size_t)(r0 + r) * 128 + tid] = a2[r];
        }
    }
}

// ---------------- edge kernel: v_pre = relu((relu(S1s+S2r)-relu(S1r+S2s)) @ A3) @ A4 + A4_b
// block = 256 threads = 4 groups of 64; each group handles one edge per iteration.
// per-thread: c4 = 4 output cols (packed f32x2 pairs), 3 time rows -> A3/A4 LDS reuse x3.
#define K1_SMEM_FLOATS (8192 + 4096 + 4 * 1536 + 4 * 768)   // 21504 floats = 84 KB
__global__ void k_edge(const int* __restrict__ bi, const int* __restrict__ si,
                       const int* __restrict__ ri,
                       const float* __restrict__ A3w, const float* __restrict__ A4w,
                       const float* __restrict__ A4b, float* __restrict__ outv) {
    extern __shared__ float sh[];
    float* A3sh = sh;                       // [128*64]
    float* A4sh = sh + 8192;                // [64*64]
    float* hdf  = sh + 8192 + 4096;         // [4][1536]
    float* dsh  = sh + 8192 + 4096 + 4*1536;// [4][768]

    int tid = threadIdx.x;
    {   // cache weights
        float4* d3 = (float4*)A3sh; const float4* s3 = (const float4*)A3w;
        for (int i = tid; i < 2048; i += 256) d3[i] = s3[i];
        float4* d4 = (float4*)A4sh; const float4* s4 = (const float4*)A4w;
        for (int i = tid; i < 1024; i += 256) d4[i] = s4[i];
    }
    int grp  = tid >> 6;        // 0..3  (edge lane)
    int gtid = tid & 63;
    int c4   = gtid & 15;       // 4-col group
    int tg   = gtid >> 4;       // 0..3 -> handles t = tg, tg+4, tg+8
    float* hdg = hdf + grp * 1536;
    float* dsg = dsh + grp * 768;
    float4* dsg4 = (float4*)dsg;
    const ulonglong2* A3v = (const ulonglong2*)A3sh;
    const ulonglong2* A4v = (const ulonglong2*)A4sh;
    float4 a4bias = ((const float4*)A4b)[c4];
    __syncthreads();

    for (int eb = blockIdx.x * 4; eb < E_; eb += gridDim.x * 4) {
        int e = eb + grp;
        int b = bi[e];
        int ns = b * N_ + si[e];
        int nr = b * N_ + ri[e];
        const float* s1s = g_S1 + (size_t)ns * TH_;
        const float* s2s = g_S2 + (size_t)ns * TH_;
        const float* s1r = g_S1 + (size_t)nr * TH_;
        const float* s2r = g_S2 + (size_t)nr * TH_;
#pragma unroll 6
        for (int i = gtid; i < 1536; i += 64) {
            float hij = fmaxf(s1s[i] + s2r[i], 0.f);
            float hji = fmaxf(s1r[i] + s2s[i], 0.f);
            hdg[i] = hij - hji;
        }
        __syncthreads();

        // d[t][c] = sum_h hdiff[t][h] * A3[h][c]
        u64 acc[3][2] = {{0ull,0ull},{0ull,0ull},{0ull,0ull}};
        const float* h0 = hdg + (tg + 0) * 128;
        const float* h1 = hdg + (tg + 4) * 128;
        const float* h2 = hdg + (tg + 8) * 128;
#pragma unroll 8
        for (int h = 0; h < 128; h++) {
            ulonglong2 a3 = A3v[h * 16 + c4];
            u64 b0 = pack2(h0[h], h0[h]);
            u64 b1 = pack2(h1[h], h1[h]);
            u64 b2 = pack2(h2[h], h2[h]);
            fma2(acc[0][0], a3.x, b0); fma2(acc[0][1], a3.y, b0);
            fma2(acc[1][0], a3.x, b1); fma2(acc[1][1], a3.y, b1);
            fma2(acc[2][0], a3.x, b2); fma2(acc[2][1], a3.y, b2);
        }
#pragma unroll
        for (int j = 0; j < 3; j++) {
            int t = tg + 4 * j;
            float2 lo = unpack2(acc[j][0]);
            float2 hi = unpack2(acc[j][1]);
            float4 rd;
            rd.x = fmaxf(lo.x, 0.f); rd.y = fmaxf(lo.y, 0.f);
            rd.z = fmaxf(hi.x, 0.f); rd.w = fmaxf(hi.y, 0.f);
            dsg4[t * 16 + c4] = rd;
        }
        __syncthreads();

        // v[t][c] = sum_k relu(d)[t][k] * A4[k][c] + A4_b[c]
        u64 vac[3][2] = {{0ull,0ull},{0ull,0ull},{0ull,0ull}};
        const float* d0 = dsg + (tg + 0) * 64;
        const float* d1 = dsg + (tg + 4) * 64;
        const float* d2 = dsg + (tg + 8) * 64;
#pragma unroll 8
        for (int k = 0; k < 64; k++) {
            ulonglong2 a4 = A4v[k * 16 + c4];
            u64 b0 = pack2(d0[k], d0[k]);
            u64 b1 = pack2(d1[k], d1[k]);
            u64 b2 = pack2(d2[k], d2[k]);
            fma2(vac[0][0], a4.x, b0); fma2(vac[0][1], a4.y, b0);
            fma2(vac[1][0], a4.x, b1); fma2(vac[1][1], a4.y, b1);
            fma2(vac[2][0], a4.x, b2); fma2(vac[2][1], a4.y, b2);
        }
#pragma unroll
        for (int j = 0; j < 3; j++) {
            int t = tg + 4 * j;
            float2 lo = unpack2(vac[j][0]);
            float2 hi = unpack2(vac[j][1]);
            float4 out;
            out.x = lo.x + a4bias.x; out.y = lo.y + a4bias.y;
            out.z = hi.x + a4bias.z; out.w = hi.y + a4bias.w;
            ((float4*)(outv + ((size_t)e * T_ + t) * 64))[c4] = out;
        }
        __syncthreads();
    }
}

// ---------------- per-sender-segment softmax over v_pre (in place in outv) ----------------
__global__ void k_softmax(float* __restrict__ v) {
    int seg = blockIdx.x;
    int beg = g_off[seg], end = g_off[seg + 1];
    if (beg == end) return;
    int tid = threadIdx.x;
    int c0 = tid, c1 = tid + 256, c2 = tid + 512;
    float m0 = -1e30f, m1 = -1e30f, m2 = -1e30f;
    for (int i = beg; i < end; i++) {
        const float* vp = v + (size_t)g_csr_s[i] * TD_;
        m0 = fmaxf(m0, vp[c0]); m1 = fmaxf(m1, vp[c1]); m2 = fmaxf(m2, vp[c2]);
    }
    float s0 = 0.f, s1 = 0.f, s2 = 0.f;
    for (int i = beg; i < end; i++) {
        const float* vp = v + (size_t)g_csr_s[i] * TD_;
        s0 += __expf(vp[c0] - m0); s1 += __expf(vp[c1] - m1); s2 += __expf(vp[c2] - m2);
    }
    float r0 = 1.f / (s0 + 1e-12f), r1 = 1.f / (s1 + 1e-12f), r2 = 1.f / (s2 + 1e-12f);
    for (int i = beg; i < end; i++) {
        float* vp = v + (size_t)g_csr_s[i] * TD_;
        vp[c0] = __expf(vp[c0] - m0) * r0;
        vp[c1] = __expf(vp[c1] - m1) * r1;
        vp[c2] = __expf(vp[c2] - m2) * r2;
    }
}

// ---------------- per-receiver-segment aggregation + x update ----------------
__global__ void k_aggregate(const float* __restrict__ x, const float* __restrict__ v,
                            const int* __restrict__ bi, const int* __restrict__ si,
                            float* __restrict__ outx) {
    int seg = blockIdx.x;                      // receiver node
    int tid = threadIdx.x;
    int beg = g_off[(SEG_ + 1) + seg], end = g_off[(SEG_ + 1) + seg + 1];
    int c0 = tid, c1 = tid + 256, c2 = tid + 512;
    float a0 = 0.f, a1 = 0.f, a2 = 0.f;
    for (int i = beg; i < end; i++) {
        int e = g_csr_r[i];
        int ns = bi[e] * N_ + si[e];
        const float* vp = v + (size_t)e * TD_;
        const float* xs = x + (size_t)ns * TD_;
        a0 = fmaf(vp[c0], xs[c0], a0);
        a1 = fmaf(vp[c1], xs[c1], a1);
        a2 = fmaf(vp[c2], xs[c2], a2);
    }
    const float* xr = x + (size_t)seg * TD_;
    float* o = outx + (size_t)seg * TD_;
    o[c0] = xr[c0] + 0.1f * (a0 - xr[c0]);
    o[c1] = xr[c1] + 0.1f * (a1 - xr[c1]);
    o[c2] = xr[c2] + 0.1f * (a2 - xr[c2]);
}

// ---------------- launch ----------------
extern "C" void kernel_launch(void* const* d_in, const int* in_sizes, int n_in,
                              void* d_out, int out_size) {
    const float* x   = (const float*)d_in[0];
    const int*   bi  = (const int*)d_in[1];
    const int*   si  = (const int*)d_in[2];
    const int*   ri  = (const int*)d_in[3];
    const float* A1w = (const float*)d_in[4];
    const float* A1b = (const float*)d_in[5];
    const float* A2w = (const float*)d_in[6];
    const float* A2b = (const float*)d_in[7];
    const float* A3w = (const float*)d_in[8];
    // d_in[9] = A3_b: cancels in z_ij - z_ji, unused
    const float* A4w = (const float*)d_in[10];
    const float* A4b = (const float*)d_in[11];

    float* outx = (float*)d_out;
    float* outv = outx + (size_t)ROWS_ * D_;   // x_updated first, then v_ij

    const int k1_smem = K1_SMEM_FLOATS * 4;    // 86016 B > 48 KB -> opt in
    cudaFuncSetAttribute(k_edge, cudaFuncAttributeMaxDynamicSharedMemorySize, k1_smem);

    k_zero<<<32, 256>>>();
    k_count<<<(E_ + 255) / 256, 256>>>(bi, si, ri);
    k_scan<<<1, 1024>>>(0);
    k_scan<<<1, 1024>>>(1);
    k_scatter<<<(E_ + 255) / 256, 256>>>(bi, si, ri);
    k_nodeproj<<<ROWS_ / 64, 128>>>(x, A1w, A1b, A2w, A2b);
    k_edge<<<296, 256, k1_smem>>>(bi, si, ri, A3w, A4w, A4b, outv);
    k_softmax<<<SEG_, 256>>>(outv);
    k_aggregate<<<SEG_, 256>>>(x, outv, bi, si, outx);
}

// round 2
// speedup vs baseline: 1.0011x; 1.0011x over previous
#include <cuda_runtime.h>
#include <cstdint>

#define B_    4
#define N_    1000
#define T_    12
#define D_    64
#define HID_  128
#define EF_   64
#define E_    64000
#define SEG_  (B_*N_)       // 4000
#define ROWS_ (SEG_*T_)     // 48000
#define TD_   (T_*D_)       // 768
#define TH_   (T_*HID_)     // 1536

typedef unsigned long long u64;

// ---------------- device scratch (no allocations allowed) ----------------
__device__ float g_S1[ROWS_ * HID_];   // x@A1 + (A1_b+A2_b), [node*T][HID]
__device__ float g_S2[ROWS_ * HID_];   // x@A2
__device__ int   g_cnt[2 * SEG_];
__device__ int   g_off[2 * (SEG_ + 1)];
__device__ int   g_cur[2 * SEG_];
__device__ int   g_csr_s[E_];
__device__ int   g_csr_r[E_];

// ---------------- f32x2 packed helpers (sm_100+ only) ----------------
__device__ __forceinline__ void fma2(u64 &d, u64 a, u64 b) {
    asm("fma.rn.f32x2 %0, %1, %2, %0;" : "+l"(d) : "l"(a), "l"(b));
}
__device__ __forceinline__ u64 pack2(float x, float y) {
    u64 r; asm("mov.b64 %0, {%1, %2};" : "=l"(r) : "f"(x), "f"(y)); return r;
}
__device__ __forceinline__ float2 unpack2(u64 v) {
    float2 r; asm("mov.b64 {%0, %1}, %2;" : "=f"(r.x), "=f"(r.y) : "l"(v)); return r;
}

// ---------------- CSR build ----------------
__global__ void k_zero() {
    int i = blockIdx.x * blockDim.x + threadIdx.x;
    if (i < 2 * SEG_) g_cnt[i] = 0;
}

__global__ void k_count(const int* __restrict__ bi, const int* __restrict__ si,
                        const int* __restrict__ ri) {
    int e = blockIdx.x * blockDim.x + threadIdx.x;
    if (e >= E_) return;
    int b = bi[e];
    atomicAdd(&g_cnt[b * N_ + si[e]], 1);
    atomicAdd(&g_cnt[SEG_ + b * N_ + ri[e]], 1);
}

// single-block exclusive scan of 4000 counts (which: 0=send, 1=recv)
__global__ void k_scan(int which) {
    const int* cnt = g_cnt + which * SEG_;
    int* off = g_off + which * (SEG_ + 1);
    int* cur = g_cur + which * SEG_;
    __shared__ int part[1024];
    int tid = threadIdx.x;
    int l[4]; int s = 0;
#pragma unroll
    for (int j = 0; j < 4; j++) {
        int idx = tid * 4 + j;
        l[j] = (idx < SEG_) ? cnt[idx] : 0;
        s += l[j];
    }
    part[tid] = s;
    __syncthreads();
    for (int o = 1; o < 1024; o <<= 1) {
        int v = part[tid];
        int a = (tid >= o) ? part[tid - o] : 0;
        __syncthreads();
        part[tid] = v + a;
        __syncthreads();
    }
    int run = (tid > 0) ? part[tid - 1] : 0;
#pragma unroll
    for (int j = 0; j < 4; j++) {
        int idx = tid * 4 + j;
        if (idx < SEG_) { off[idx] = run; cur[idx] = run; run += l[j]; }
    }
    if (tid == 1023) off[SEG_] = part[1023];
}

__global__ void k_scatter(const int* __restrict__ bi, const int* __restrict__ si,
                          const int* __restrict__ ri) {
    int e = blockIdx.x * blockDim.x + threadIdx.x;
    if (e >= E_) return;
    int b = bi[e];
    int ps = atomicAdd(&g_cur[b * N_ + si[e]], 1);
    g_csr_s[ps] = e;
    int pr = atomicAdd(&g_cur[SEG_ + b * N_ + ri[e]], 1);
    g_csr_r[pr] = e;
}

// ---------------- node projection: S1 = x@A1 + (A1_b+A2_b), S2 = x@A2 ----------------
// 375 blocks x 128 threads; weights cached in shared; 128 rows/block, 8 rows/pass.
#define NP_SMEM_FLOATS (8192 + 8192 + 512)
__global__ void k_nodeproj(const float* __restrict__ x,
                           const float* __restrict__ A1w, const float* __restrict__ A1b,
                           const float* __restrict__ A2w, const float* __restrict__ A2b) {
    extern __shared__ float shp[];
    float* A1sh = shp;
    float* A2sh = shp + 8192;
    float* xsh  = shp + 16384;     // [8*64]
    int tid = threadIdx.x;         // 0..127 = output column h
    {
        float4* d1 = (float4*)A1sh; const float4* s1 = (const float4*)A1w;
        for (int i = tid; i < 2048; i += 128) d1[i] = s1[i];
        float4* d2 = (float4*)A2sh; const float4* s2 = (const float4*)A2w;
        for (int i = tid; i < 2048; i += 128) d2[i] = s2[i];
    }
    float b12 = A1b[tid] + A2b[tid];
    int rowBase = blockIdx.x * 128;
    for (int p = 0; p < 16; p++) {
        int r0 = rowBase + p * 8;
        __syncthreads();
        for (int i = tid; i < 512; i += 128) xsh[i] = x[(size_t)r0 * 64 + i];
        __syncthreads();
        float a1[8], a2[8];
#pragma unroll
        for (int r = 0; r < 8; r++) { a1[r] = b12; a2[r] = 0.f; }
#pragma unroll 4
        for (int d = 0; d < 64; d++) {
            float w1 = A1sh[d * 128 + tid];
            float w2 = A2sh[d * 128 + tid];
#pragma unroll
            for (int r = 0; r < 8; r++) {
                float xv = xsh[r * 64 + d];
                a1[r] = fmaf(xv, w1, a1[r]);
                a2[r] = fmaf(xv, w2, a2[r]);
            }
        }
#pragma unroll
        for (int r = 0; r < 8; r++) {
            g_S1[(size_t)(r0 + r) * 128 + tid] = a1[r];
            g_S2[(size_t)(r0 + r) * 128 + tid] = a2[r];
        }
    }
}

// ---------------- fused edge MLP + segment softmax ----------------
// One block per sender segment. 256 threads = 4 groups x 64; group handles one
// edge per batch. Online (m,s) per column in registers (3 cols/thread), then a
// single in-place normalize pass over the segment's edges (L2-hot).
#define FK_SMEM_FLOATS (8192 + 4096 + 1536 + 1536 + 4*1536 + 4*768 + 4*768)  // 27648 = 108 KB
__global__ void k_fused(const int* __restrict__ bi, const int* __restrict__ ri,
                        const float* __restrict__ A3w, const float* __restrict__ A4w,
                        const float* __restrict__ A4b, float* __restrict__ outv) {
    extern __shared__ float sh[];
    float* A3sh = sh;                        // [128*64]
    float* A4sh = sh + 8192;                 // [64*64]
    float* S1s  = sh + 8192 + 4096;          // [1536]
    float* S2s  = S1s + 1536;                // [1536]
    float* hdf  = S2s + 1536;                // [4][1536]
    float* dsh  = hdf + 4 * 1536;            // [4][768]
    float* vb   = dsh + 4 * 768;             // [4][768]

    int tid = threadIdx.x;
    int seg = blockIdx.x;
    {   // cache weights
        float4* d3 = (float4*)A3sh; const float4* s3 = (const float4*)A3w;
        for (int i = tid; i < 2048; i += 256) d3[i] = s3[i];
        float4* d4 = (float4*)A4sh; const float4* s4 = (const float4*)A4w;
        for (int i = tid; i < 1024; i += 256) d4[i] = s4[i];
        // stage sender rows
        const float4* g1 = (const float4*)(g_S1 + (size_t)seg * TH_);
        const float4* g2 = (const float4*)(g_S2 + (size_t)seg * TH_);
        float4* S1s4 = (float4*)S1s; float4* S2s4 = (float4*)S2s;
        for (int i = tid; i < 384; i += 256) { S1s4[i] = g1[i]; S2s4[i] = g2[i]; }
    }
    int beg = g_off[seg], end = g_off[seg + 1];
    __syncthreads();
    if (beg == end) return;

    int grp  = tid >> 6;        // 0..3 (edge lane within batch)
    int gtid = tid & 63;
    int c4   = gtid & 15;       // 4-col group
    int tg   = gtid >> 4;       // 0..3 -> t = tg, tg+4, tg+8
    float* hdg = hdf + grp * 1536;
    float* dsg = dsh + grp * 768;
    float4* dsg4 = (float4*)dsg;
    float4* vbg4 = (float4*)(vb + grp * 768);
    const ulonglong2* A3v = (const ulonglong2*)A3sh;
    const ulonglong2* A4v = (const ulonglong2*)A4sh;
    const float4* S1s4 = (const float4*)S1s;
    const float4* S2s4 = (const float4*)S2s;
    float4 a4bias = ((const float4*)A4b)[c4];

    float m[3] = {-1e30f, -1e30f, -1e30f};
    float s[3] = {0.f, 0.f, 0.f};

    int nbat = (end - beg + 3) >> 2;
    for (int b = 0; b < nbat; b++) {
        int i = beg + b * 4 + grp;
        bool valid = (i < end);
        int e = 0;
        if (valid) {
            e = g_csr_s[i];
            int nr = bi[e] * N_ + ri[e];
            const float4* s1r = (const float4*)(g_S1 + (size_t)nr * TH_);
            const float4* s2r = (const float4*)(g_S2 + (size_t)nr * TH_);
            float4* hd4 = (float4*)hdg;
#pragma unroll 6
            for (int i4 = gtid; i4 < 384; i4 += 64) {
                float4 a = S1s4[i4], br = s2r[i4], c = s1r[i4], d = S2s4[i4];
                float4 o;
                o.x = fmaxf(a.x + br.x, 0.f) - fmaxf(c.x + d.x, 0.f);
                o.y = fmaxf(a.y + br.y, 0.f) - fmaxf(c.y + d.y, 0.f);
                o.z = fmaxf(a.z + br.z, 0.f) - fmaxf(c.z + d.z, 0.f);
                o.w = fmaxf(a.w + br.w, 0.f) - fmaxf(c.w + d.w, 0.f);
                hd4[i4] = o;
            }
        }
        __syncthreads();

        if (valid) {
            // d[t][c] = sum_h hdiff[t][h] * A3[h][c]
            u64 acc[3][2] = {{0ull,0ull},{0ull,0ull},{0ull,0ull}};
            const float* h0 = hdg + (tg + 0) * 128;
            const float* h1 = hdg + (tg + 4) * 128;
            const float* h2 = hdg + (tg + 8) * 128;
#pragma unroll 8
            for (int h = 0; h < 128; h++) {
                ulonglong2 a3 = A3v[h * 16 + c4];
                u64 b0 = pack2(h0[h], h0[h]);
                u64 b1 = pack2(h1[h], h1[h]);
                u64 b2 = pack2(h2[h], h2[h]);
                fma2(acc[0][0], a3.x, b0); fma2(acc[0][1], a3.y, b0);
                fma2(acc[1][0], a3.x, b1); fma2(acc[1][1], a3.y, b1);
                fma2(acc[2][0], a3.x, b2); fma2(acc[2][1], a3.y, b2);
            }
#pragma unroll
            for (int j = 0; j < 3; j++) {
                int t = tg + 4 * j;
                float2 lo = unpack2(acc[j][0]);
                float2 hi = unpack2(acc[j][1]);
                float4 rd;
                rd.x = fmaxf(lo.x, 0.f); rd.y = fmaxf(lo.y, 0.f);
                rd.z = fmaxf(hi.x, 0.f); rd.w = fmaxf(hi.y, 0.f);
                dsg4[t * 16 + c4] = rd;
            }
        }
        __syncthreads();

        if (valid) {
            // v[t][c] = sum_k relu(d)[t][k] * A4[k][c] + A4_b[c]
            u64 vac[3][2] = {{0ull,0ull},{0ull,0ull},{0ull,0ull}};
            const float* d0 = dsg + (tg + 0) * 64;
            const float* d1 = dsg + (tg + 4) * 64;
            const float* d2 = dsg + (tg + 8) * 64;
#pragma unroll 8
            for (int k = 0; k < 64; k++) {
                ulonglong2 a4 = A4v[k * 16 + c4];
                u64 b0 = pack2(d0[k], d0[k]);
                u64 b1 = pack2(d1[k], d1[k]);
                u64 b2 = pack2(d2[k], d2[k]);
                fma2(vac[0][0], a4.x, b0); fma2(vac[0][1], a4.y, b0);
                fma2(vac[1][0], a4.x, b1); fma2(vac[1][1], a4.y, b1);
                fma2(vac[2][0], a4.x, b2); fma2(vac[2][1], a4.y, b2);
            }
#pragma unroll
            for (int j = 0; j < 3; j++) {
                int t = tg + 4 * j;
                float2 lo = unpack2(vac[j][0]);
                float2 hi = unpack2(vac[j][1]);
                float4 out;
                out.x = lo.x + a4bias.x; out.y = lo.y + a4bias.y;
                out.z = hi.x + a4bias.z; out.w = hi.y + a4bias.w;
                vbg4[t * 16 + c4] = out;
                ((float4*)(outv + ((size_t)e * T_ + t) * 64))[c4] = out;
            }
        }
        __syncthreads();

        // online (m, s) update across this batch's edges — all 256 threads
        int nb = end - (beg + b * 4);
        if (nb > 4) nb = 4;
#pragma unroll
        for (int j = 0; j < 3; j++) {
            int col = tid + j * 256;
            float vv[4];
            float bm = -1e30f;
            for (int k = 0; k < nb; k++) {
                vv[k] = vb[k * 768 + col];
                bm = fmaxf(bm, vv[k]);
            }
            float mn = fmaxf(m[j], bm);
            float acc = s[j] * __expf(m[j] - mn);
            for (int k = 0; k < nb; k++) acc += __expf(vv[k] - mn);
            m[j] = mn; s[j] = acc;
        }
        __syncthreads();
    }

    // in-place normalize (reads are L2-hot: this block just wrote them)
    float r[3];
#pragma unroll
    for (int j = 0; j < 3; j++) r[j] = 1.f / (s[j] + 1e-12f);
    for (int i = beg; i < end; i++) {
        int e = g_csr_s[i];
        float* vp = outv + (size_t)e * TD_;
#pragma unroll
        for (int j = 0; j < 3; j++) {
            int col = tid + j * 256;
            vp[col] = __expf(vp[col] - m[j]) * r[j];
        }
    }
}

// ---------------- per-receiver-segment aggregation + x update ----------------
__global__ void k_aggregate(const float* __restrict__ x, const float* __restrict__ v,
                            const int* __restrict__ bi, const int* __restrict__ si,
                            float* __restrict__ outx) {
    int seg = blockIdx.x;                      // receiver node
    int tid = threadIdx.x;
    int beg = g_off[(SEG_ + 1) + seg], end = g_off[(SEG_ + 1) + seg + 1];
    int c0 = tid, c1 = tid + 256, c2 = tid + 512;
    float a0 = 0.f, a1 = 0.f, a2 = 0.f;
    for (int i = beg; i < end; i++) {
        int e = g_csr_r[i];
        int ns = bi[e] * N_ + si[e];
        const float* vp = v + (size_t)e * TD_;
        const float* xs = x + (size_t)ns * TD_;
        a0 = fmaf(vp[c0], xs[c0], a0);
        a1 = fmaf(vp[c1], xs[c1], a1);
        a2 = fmaf(vp[c2], xs[c2], a2);
    }
    const float* xr = x + (size_t)seg * TD_;
    float* o = outx + (size_t)seg * TD_;
    o[c0] = xr[c0] + 0.1f * (a0 - xr[c0]);
    o[c1] = xr[c1] + 0.1f * (a1 - xr[c1]);
    o[c2] = xr[c2] + 0.1f * (a2 - xr[c2]);
}

// ---------------- launch ----------------
extern "C" void kernel_launch(void* const* d_in, const int* in_sizes, int n_in,
                              void* d_out, int out_size) {
    const float* x   = (const float*)d_in[0];
    const int*   bi  = (const int*)d_in[1];
    const int*   si  = (const int*)d_in[2];
    const int*   ri  = (const int*)d_in[3];
    const float* A1w = (const float*)d_in[4];
    const float* A1b = (const float*)d_in[5];
    const float* A2w = (const float*)d_in[6];
    const float* A2b = (const float*)d_in[7];
    const float* A3w = (const float*)d_in[8];
    // d_in[9] = A3_b: cancels in z_ij - z_ji, unused
    const float* A4w = (const float*)d_in[10];
    const float* A4b = (const float*)d_in[11];

    float* outx = (float*)d_out;
    float* outv = outx + (size_t)ROWS_ * D_;   // x_updated first, then v_ij

    const int np_smem = NP_SMEM_FLOATS * 4;    // ~66 KB
    const int fk_smem = FK_SMEM_FLOATS * 4;    // ~108 KB
    cudaFuncSetAttribute(k_nodeproj, cudaFuncAttributeMaxDynamicSharedMemorySize, np_smem);
    cudaFuncSetAttribute(k_fused,    cudaFuncAttributeMaxDynamicSharedMemorySize, fk_smem);

    k_zero<<<32, 256>>>();
    k_count<<<(E_ + 255) / 256, 256>>>(bi, si, ri);
    k_scan<<<1, 1024>>>(0);
    k_scan<<<1, 1024>>>(1);
    k_scatter<<<(E_ + 255) / 256, 256>>>(bi, si, ri);
    k_nodeproj<<<ROWS_ / 128, 128, np_smem>>>(x, A1w, A1b, A2w, A2b);
    k_fused<<<SEG_, 256, fk_smem>>>(bi, ri, A3w, A4w, A4b, outv);
    k_aggregate<<<SEG_, 256>>>(x, outv, bi, si, outx);
}